// round 2
// baseline (speedup 1.0000x reference)
#include <cuda_runtime.h>
#include <math.h>

// Problem constants
#define MM   8192        // bs*n
#define DD   768         // feature dim
#define KD   64          // Psi dim
#define KF   32          // feature top-k
#define HW   1024        // pixels per image
#define BSZ  8           // batch

// -------- device scratch (static, no runtime alloc) --------
__device__ float g_Xn[(size_t)MM*DD];            // normalized features  (25 MB)
__device__ float g_A[(size_t)MM*MM];             // clamped sim matrix   (268 MB)
__device__ float g_topv[MM*KF];
__device__ int   g_topi[MM*KF];
__device__ float g_deg[MM];
__device__ float g_drs[MM];
__device__ unsigned char g_adj[(size_t)BSZ*HW*HW];  // pixel adjacency (8.4 MB)
__device__ float g_deg2[MM];
__device__ float g_drs2[MM];
__device__ float g_gP[MM*KD];                    // gram_total @ Psi (sparse accumulated)
__device__ float g_R[KD*KD];

// -------- zero scratch that accumulates --------
__global__ void zero_kernel() {
    int idx = blockIdx.x * blockDim.x + threadIdx.x;
    int n   = gridDim.x * blockDim.x;
    for (int i = idx; i < MM; i += n) { g_deg[i] = 0.f; g_deg2[i] = 0.f; }
    for (int i = idx; i < MM*KD; i += n) g_gP[i] = 0.f;
    for (int i = idx; i < KD*KD; i += n) g_R[i] = 0.f;
    unsigned int* aj = (unsigned int*)g_adj;
    for (int i = idx; i < (int)((size_t)BSZ*HW*HW/4); i += n) aj[i] = 0u;
}

// -------- row-normalize features (1 warp / row) --------
__global__ void normalize_kernel(const float* __restrict__ hf) {
    int row  = blockIdx.x * 8 + (threadIdx.x >> 5);
    int lane = threadIdx.x & 31;
    const float* x = hf + (size_t)row * DD;
    float s = 0.f;
    for (int k = lane; k < DD; k += 32) { float v = x[k]; s += v * v; }
    #pragma unroll
    for (int o = 16; o > 0; o >>= 1) s += __shfl_xor_sync(0xffffffffu, s, o);
    float inv = 1.0f / sqrtf(s);
    float* y = g_Xn + (size_t)row * DD;
    for (int k = lane; k < DD; k += 32) y[k] = x[k] * inv;
}

// -------- symmetric SGEMM: A = clamp(Xn Xn^T), upper-tri tiles only --------
__global__ __launch_bounds__(256) void gemm_sym_kernel() {
    int t  = blockIdx.x;
    int bc = (int)((sqrtf(8.0f * (float)t + 1.0f) - 1.0f) * 0.5f);
    while ((bc + 1) * (bc + 2) / 2 <= t) bc++;
    while (bc * (bc + 1) / 2 > t) bc--;
    int br = t - bc * (bc + 1) / 2;          // br <= bc

    __shared__ float As[16][132];
    __shared__ float Bs[16][132];

    int tid = threadIdx.x;
    int r   = tid >> 2, kq = tid & 3;        // loader mapping
    int tx  = tid & 15, ty = tid >> 4;       // compute mapping (16x16 threads, 8x8 each)

    const float* Abase = g_Xn + (size_t)(br * 128) * DD;
    const float* Bbase = g_Xn + (size_t)(bc * 128) * DD;

    float acc[8][8];
    #pragma unroll
    for (int m = 0; m < 8; m++)
        #pragma unroll
        for (int n = 0; n < 8; n++) acc[m][n] = 0.f;

    for (int k0 = 0; k0 < DD; k0 += 16) {
        float4 a0 = *(const float4*)(Abase + (size_t)r        * DD + k0 + kq * 4);
        float4 a1 = *(const float4*)(Abase + (size_t)(r + 64) * DD + k0 + kq * 4);
        float4 b0 = *(const float4*)(Bbase + (size_t)r        * DD + k0 + kq * 4);
        float4 b1 = *(const float4*)(Bbase + (size_t)(r + 64) * DD + k0 + kq * 4);
        __syncthreads();
        As[kq*4+0][r] = a0.x; As[kq*4+1][r] = a0.y; As[kq*4+2][r] = a0.z; As[kq*4+3][r] = a0.w;
        As[kq*4+0][r+64] = a1.x; As[kq*4+1][r+64] = a1.y; As[kq*4+2][r+64] = a1.z; As[kq*4+3][r+64] = a1.w;
        Bs[kq*4+0][r] = b0.x; Bs[kq*4+1][r] = b0.y; Bs[kq*4+2][r] = b0.z; Bs[kq*4+3][r] = b0.w;
        Bs[kq*4+0][r+64] = b1.x; Bs[kq*4+1][r+64] = b1.y; Bs[kq*4+2][r+64] = b1.z; Bs[kq*4+3][r+64] = b1.w;
        __syncthreads();
        #pragma unroll
        for (int kk = 0; kk < 16; kk++) {
            float a[8], b[8];
            *(float4*)&a[0] = *(const float4*)&As[kk][ty * 8];
            *(float4*)&a[4] = *(const float4*)&As[kk][ty * 8 + 4];
            *(float4*)&b[0] = *(const float4*)&Bs[kk][tx * 8];
            *(float4*)&b[4] = *(const float4*)&Bs[kk][tx * 8 + 4];
            #pragma unroll
            for (int m = 0; m < 8; m++)
                #pragma unroll
                for (int n = 0; n < 8; n++) acc[m][n] += a[m] * b[n];
        }
    }

    #pragma unroll
    for (int m = 0; m < 8; m++) {
        int i = br * 128 + ty * 8 + m;
        #pragma unroll
        for (int n = 0; n < 8; n++) {
            int j = bc * 128 + tx * 8 + n;
            float v = acc[m][n];
            v = (i == j) ? 0.0f : fmaxf(v, 0.0f);   // diag=-inf then clamp -> 0
            g_A[(size_t)i * MM + j] = v;
            g_A[(size_t)j * MM + i] = v;            // symmetric fill
        }
    }
}

// -------- per-row top-32 (iterative argmax, tie -> lower index) --------
__global__ __launch_bounds__(256) void topk_kernel() {
    int row = blockIdx.x;
    __shared__ float s[MM];       // 32 KB
    __shared__ float bv[256];
    __shared__ int   bi[256];
    int tid = threadIdx.x;
    const float* arow = g_A + (size_t)row * MM;
    for (int j = tid; j < MM; j += 256) s[j] = arow[j];
    __syncthreads();
    for (int it = 0; it < KF; it++) {
        float best = -1.0f; int bidx = MM;
        for (int j = tid; j < MM; j += 256) {
            float v = s[j];
            if (v > best) { best = v; bidx = j; }   // strict > keeps lowest j on ties
        }
        bv[tid] = best; bi[tid] = bidx;
        __syncthreads();
        for (int s2 = 128; s2 > 0; s2 >>= 1) {
            if (tid < s2) {
                if (bv[tid+s2] > bv[tid] || (bv[tid+s2] == bv[tid] && bi[tid+s2] < bi[tid])) {
                    bv[tid] = bv[tid+s2]; bi[tid] = bi[tid+s2];
                }
            }
            __syncthreads();
        }
        if (tid == 0) {
            g_topv[row * KF + it] = bv[0];
            g_topi[row * KF + it] = bi[0];
            s[bi[0]] = -1.0e30f;
        }
        __syncthreads();
    }
}

// -------- feature degrees: deg = rowsum((res+res^T)/2) --------
__global__ void feat_deg_kernel() {
    int e = blockIdx.x * blockDim.x + threadIdx.x;
    if (e >= MM * KF) return;
    int i = e >> 5; int j = g_topi[e]; float v = g_topv[e];
    atomicAdd(&g_deg[i], 0.5f * v);
    atomicAdd(&g_deg[j], 0.5f * v);
}

// -------- pixel adjacency: per (batch,row) top-10 for both (k,dw) configs --------
__global__ __launch_bounds__(256) void pixel_adj_kernel(const float* __restrict__ im) {
    int blk = blockIdx.x; int b = blk >> 10; int i = blk & 1023;
    int tid = threadIdx.x;
    __shared__ float sf[3][HW];
    __shared__ float sd[HW];
    __shared__ float bv[256];
    __shared__ int   bi[256];
    for (int idx = tid; idx < 3 * HW; idx += 256) {
        int c = idx >> 10; int j = idx & 1023;
        sf[c][j] = (im[((size_t)b * 3 + c) * HW + j] + 1.0f) * 0.5f;
    }
    __syncthreads();
    float xi = (float)(i & 31) * (1.0f / 31.0f);
    float yi = (float)(i >> 5) * (1.0f / 31.0f);
    float f0i = sf[0][i], f1i = sf[1][i], f2i = sf[2][i];

    for (int cfg = 0; cfg < 2; cfg++) {
        float dw = (cfg == 0) ? 2.0f : 0.1f;
        float xiw = xi * dw, yiw = yi * dw;
        float sqi = f0i*f0i + f1i*f1i + f2i*f2i + xiw*xiw + yiw*yiw;
        for (int j = tid; j < HW; j += 256) {
            float xj = (float)(j & 31) * (1.0f / 31.0f) * dw;
            float yj = (float)(j >> 5) * (1.0f / 31.0f) * dw;
            float f0 = sf[0][j], f1 = sf[1][j], f2 = sf[2][j];
            float sqj = f0*f0 + f1*f1 + f2*f2 + xj*xj + yj*yj;
            float dot = f0i*f0 + f1i*f1 + f2i*f2 + xiw*xj + yiw*yj;
            sd[j] = sqi + sqj - 2.0f * dot;
        }
        __syncthreads();
        if (tid == 0) sd[i] = 3.0e38f;            // exclude diag
        __syncthreads();
        for (int it = 0; it < 10; it++) {
            float best = 3.0e38f; int bidx = HW;
            for (int j = tid; j < HW; j += 256) {
                float v = sd[j];
                if (v < best) { best = v; bidx = j; }
            }
            bv[tid] = best; bi[tid] = bidx;
            __syncthreads();
            for (int s2 = 128; s2 > 0; s2 >>= 1) {
                if (tid < s2) {
                    if (bv[tid+s2] < bv[tid] || (bv[tid+s2] == bv[tid] && bi[tid+s2] < bi[tid])) {
                        bv[tid] = bv[tid+s2]; bi[tid] = bi[tid+s2];
                    }
                }
                __syncthreads();
            }
            if (tid == 0) {
                int js = bi[0];
                g_adj[(size_t)b * HW * HW + (size_t)i  * HW + js] = 1;
                g_adj[(size_t)b * HW * HW + (size_t)js * HW + i ] = 1;
                sd[js] = 3.0e38f;
            }
            __syncthreads();
        }
        __syncthreads();
    }
}

// -------- pixel degrees (1 warp / row) --------
__global__ void pixel_deg_kernel() {
    int g    = blockIdx.x * 8 + (threadIdx.x >> 5);
    int lane = threadIdx.x & 31;
    int b = g >> 10, i = g & 1023;
    const unsigned char* row = g_adj + (size_t)b * HW * HW + (size_t)i * HW;
    float s = 0.f;
    for (int j = lane; j < HW; j += 32) s += (float)row[j];
    #pragma unroll
    for (int o = 16; o > 0; o >>= 1) s += __shfl_xor_sync(0xffffffffu, s, o);
    if (lane == 0) g_deg2[g] = s;
}

__global__ void drs_kernel() {
    int i = blockIdx.x * 256 + threadIdx.x;
    if (i < MM) {
        g_drs[i]  = 1.0f / sqrtf(g_deg[i]);
        g_drs2[i] = 1.0f / sqrtf(g_deg2[i]);
    }
}

// -------- gP += feature-gram @ Psi (sparse scatter, 4 entries/block) --------
__global__ __launch_bounds__(256) void gP_feat_kernel(const float* __restrict__ Psi) {
    int e = blockIdx.x * 4 + (threadIdx.x >> 6);
    int a = threadIdx.x & 63;
    int i = e >> 5; int j = g_topi[e]; float v = g_topv[e];
    float w = 0.5f * v * g_drs[i] * g_drs[j];
    atomicAdd(&g_gP[i * KD + a], w * Psi[(size_t)j * KD + a]);
    atomicAdd(&g_gP[j * KD + a], w * Psi[(size_t)i * KD + a]);
}

// -------- gP += 0.05 * pixel-gram @ Psi (row-owned, no atomics) --------
__global__ void gP_pix_kernel(const float* __restrict__ Psi) {
    int g = blockIdx.x; int b = g >> 10; int a = threadIdx.x;   // 64 threads
    __shared__ unsigned char srow[HW];
    const unsigned char* row = g_adj + (size_t)b * HW * HW + (size_t)(g & 1023) * HW;
    for (int j = a; j < HW / 4; j += 64)
        ((unsigned int*)srow)[j] = ((const unsigned int*)row)[j];
    __syncthreads();
    float wb  = 0.05f * g_drs2[g];
    float acc = 0.f;
    int base  = b * HW;
    for (int j = 0; j < HW; j++) {
        if (srow[j]) acc += wb * g_drs2[base + j] * Psi[(size_t)(base + j) * KD + a];
    }
    g_gP[g * KD + a] += acc;
}

// -------- R0 = Psi^T gP  (64x64) --------
__global__ __launch_bounds__(256) void R_kernel(const float* __restrict__ Psi) {
    __shared__ float sp[KD], sg[KD];
    int tid = threadIdx.x;
    int a = tid >> 2; int b0 = (tid & 3) * 16;
    float acc[16];
    #pragma unroll
    for (int bb = 0; bb < 16; bb++) acc[bb] = 0.f;
    int i0 = blockIdx.x * 128;
    for (int i = i0; i < i0 + 128; i++) {
        if (tid < KD) { sp[tid] = Psi[(size_t)i * KD + tid]; sg[tid] = g_gP[i * KD + tid]; }
        __syncthreads();
        float pa = sp[a];
        #pragma unroll
        for (int bb = 0; bb < 16; bb++) acc[bb] += pa * sg[b0 + bb];
        __syncthreads();
    }
    #pragma unroll
    for (int bb = 0; bb < 16; bb++) atomicAdd(&g_R[a * 64 + b0 + bb], acc[bb]);
}

// -------- scalars: loss = -T*tr/kdim ; reg = T^2 * sum(triu^2,1)/kdim --------
__global__ void final_kernel(float* out, int out_size) {
    __shared__ float str[256], srg[256];
    int tid = threadIdx.x;
    float tr = 0.f, rg = 0.f;
    for (int idx = tid; idx < KD * KD; idx += 256) {
        int a = idx >> 6, bcol = idx & 63;
        float v = g_R[idx];
        if (a == bcol) tr += v;
        else if (bcol > a) { float x = 10.0f * v; rg += x * x; }
    }
    str[tid] = tr; srg[tid] = rg;
    __syncthreads();
    for (int s = 128; s > 0; s >>= 1) {
        if (tid < s) { str[tid] += str[tid + s]; srg[tid] += srg[tid + s]; }
        __syncthreads();
    }
    for (int i = tid; i < out_size; i += 256) out[i] = 0.0f;
    __syncthreads();
    if (tid == 0) {
        if (out_size > 0) out[0] = -10.0f * str[0] / 64.0f;
        if (out_size > 1) out[1] = srg[0] / 64.0f;
    }
}

extern "C" void kernel_launch(void* const* d_in, const int* in_sizes, int n_in,
                              void* d_out, int out_size) {
    const float* hf  = (const float*)d_in[0];   // (8,1024,768)
    const float* Psi = (const float*)d_in[1];   // (8,1024,64)
    const float* im  = (const float*)d_in[2];   // (8,3,32,32)
    float* out = (float*)d_out;

    zero_kernel<<<2048, 256>>>();
    normalize_kernel<<<MM / 8, 256>>>(hf);
    gemm_sym_kernel<<<(64 * 65) / 2, 256>>>();
    topk_kernel<<<MM, 256>>>();
    feat_deg_kernel<<<(MM * KF) / 256, 256>>>();
    pixel_adj_kernel<<<BSZ * HW, 256>>>(im);
    pixel_deg_kernel<<<MM / 8, 256>>>();
    drs_kernel<<<MM / 256, 256>>>();
    gP_feat_kernel<<<(MM * KF) / 4, 256>>>(Psi);
    gP_pix_kernel<<<MM, 64>>>(Psi);
    R_kernel<<<MM / 128, 256>>>(Psi);
    final_kernel<<<1, 256>>>(out, out_size);
}